// round 5
// baseline (speedup 1.0000x reference)
#include <cuda_runtime.h>
#include <cuda_bf16.h>

// Problem: B=64, T=4096, D=256
//   mids[b,d]  = sum_e W[d,e] * q[b,e]
//   s[b,t]     = tanh( sum_d k[b,t,d]*mids[b,d] + bias )
//   e[b,t]     = exp(s[b,t]) * m[b,t]     (max-subtraction cancels: tanh bounded)
//   attn[b,t]  = e[b,t] / sum_t e[b,t]
//
// Inputs: q[B,D], k[B,T,D], m[B,T], W[D,D], bias[1]   Output: attn[B,T] f32

#define BATCH 64
#define TT    4096
#define DD    256

__device__ float g_mids[BATCH * DD];

// ---------------- Kernel A: mids = W @ q ------------------------------------
// grid = (D/32, B/2) = (8,32), block = 256 (8 warps).
// Warp computes 4 d-outputs for 2 batches (8 accumulators): 8 W-row LDG.128 +
// 4 q LDG.128 per lane, all independent. Halves W L2 traffic vs 1-batch warps.
__global__ void kA_mids(const float* __restrict__ q,
                        const float* __restrict__ W) {
    const int tid  = threadIdx.x;
    const int warp = tid >> 5;
    const int lane = tid & 31;

    cudaTriggerProgrammaticLaunchCompletion();

    const int b0     = blockIdx.y * 2;
    const int d_base = blockIdx.x * 32 + warp * 4;

    const float4* q0 = reinterpret_cast<const float4*>(q + b0 * DD);
    const float4* q1 = reinterpret_cast<const float4*>(q + (b0 + 1) * DD);
    const float4 xa0 = __ldg(q0 + lane);
    const float4 xa1 = __ldg(q0 + lane + 32);
    const float4 xb0 = __ldg(q1 + lane);
    const float4 xb1 = __ldg(q1 + lane + 32);

    float accA[4], accB[4];
#pragma unroll
    for (int i = 0; i < 4; ++i) {
        const float4* Wrow = reinterpret_cast<const float4*>(W + (d_base + i) * DD);
        float4 w0 = __ldg(Wrow + lane);
        float4 w1 = __ldg(Wrow + lane + 32);
        accA[i] = w0.x * xa0.x + w0.y * xa0.y + w0.z * xa0.z + w0.w * xa0.w
                + w1.x * xa1.x + w1.y * xa1.y + w1.z * xa1.z + w1.w * xa1.w;
        accB[i] = w0.x * xb0.x + w0.y * xb0.y + w0.z * xb0.z + w0.w * xb0.w
                + w1.x * xb1.x + w1.y * xb1.y + w1.z * xb1.z + w1.w * xb1.w;
    }

#pragma unroll
    for (int off = 16; off > 0; off >>= 1) {
#pragma unroll
        for (int i = 0; i < 4; ++i) {
            accA[i] += __shfl_down_sync(0xffffffffu, accA[i], off);
            accB[i] += __shfl_down_sync(0xffffffffu, accB[i], off);
        }
    }

    if (lane == 0) {
        reinterpret_cast<float4*>(g_mids + b0 * DD + d_base)[0] =
            make_float4(accA[0], accA[1], accA[2], accA[3]);
        reinterpret_cast<float4*>(g_mids + (b0 + 1) * DD + d_base)[0] =
            make_float4(accB[0], accB[1], accB[2], accB[3]);
    }
}

// ---------------- Kernel B: e[b,t] = exp(tanh(k.mids + bias)) * m -------------
// grid = (T/32, B), block = 256 (8 warps). FOUR t's per warp -> 8 independent
// LDG.128 per lane front-batched (deep L1tex queue). Block covers 32
// contiguous t's (32KB of k). PDL secondary: all k/m loads issue before the
// grid-dependency sync so they overlap kA's execution.
__global__ void kB_scores(const float* __restrict__ k,
                          const float* __restrict__ m,
                          const float* __restrict__ bias,
                          float* __restrict__ e_out) {
    __shared__ float smids[DD];
    __shared__ float4 se4[8];
    const int b    = blockIdx.y;
    const int tid  = threadIdx.x;
    const int warp = tid >> 5;
    const int lane = tid & 31;

    const int t0 = blockIdx.x * 32 + warp * 4;

    const float4* kr = reinterpret_cast<const float4*>(
        k + ((size_t)b * TT + t0) * DD);

    // 8 independent loads, issued before the dependency sync.
    float4 r00 = kr[lane];            float4 r01 = kr[lane + 32];
    float4 r10 = kr[lane + 64];       float4 r11 = kr[lane + 96];
    float4 r20 = kr[lane + 128];      float4 r21 = kr[lane + 160];
    float4 r30 = kr[lane + 192];      float4 r31 = kr[lane + 224];
    float4 mw = make_float4(0.f, 0.f, 0.f, 0.f);
    if (lane == 0)
        mw = *reinterpret_cast<const float4*>(m + (size_t)b * TT + t0);

    cudaGridDependencySynchronize();

    smids[tid] = g_mids[b * DD + tid];
    __syncthreads();

    const float4* mv = reinterpret_cast<const float4*>(smids);
    float4 m0 = mv[lane];
    float4 m1 = mv[lane + 32];

    float acc0 = r00.x * m0.x + r00.y * m0.y + r00.z * m0.z + r00.w * m0.w
               + r01.x * m1.x + r01.y * m1.y + r01.z * m1.z + r01.w * m1.w;
    float acc1 = r10.x * m0.x + r10.y * m0.y + r10.z * m0.z + r10.w * m0.w
               + r11.x * m1.x + r11.y * m1.y + r11.z * m1.z + r11.w * m1.w;
    float acc2 = r20.x * m0.x + r20.y * m0.y + r20.z * m0.z + r20.w * m0.w
               + r21.x * m1.x + r21.y * m1.y + r21.z * m1.z + r21.w * m1.w;
    float acc3 = r30.x * m0.x + r30.y * m0.y + r30.z * m0.z + r30.w * m0.w
               + r31.x * m1.x + r31.y * m1.y + r31.z * m1.z + r31.w * m1.w;

#pragma unroll
    for (int off = 16; off > 0; off >>= 1) {
        acc0 += __shfl_down_sync(0xffffffffu, acc0, off);
        acc1 += __shfl_down_sync(0xffffffffu, acc1, off);
        acc2 += __shfl_down_sync(0xffffffffu, acc2, off);
        acc3 += __shfl_down_sync(0xffffffffu, acc3, off);
    }

    if (lane == 0) {
        const float bb = bias[0];
        se4[warp] = make_float4(__expf(tanhf(acc0 + bb)) * mw.x,
                                __expf(tanhf(acc1 + bb)) * mw.y,
                                __expf(tanhf(acc2 + bb)) * mw.z,
                                __expf(tanhf(acc3 + bb)) * mw.w);
    }
    __syncthreads();

    if (tid < 8)
        reinterpret_cast<float4*>(e_out + (size_t)b * TT + blockIdx.x * 32)[tid]
            = se4[tid];
}

// ---------------- Kernel C: per-batch normalize (float4, deterministic) -------
// grid = B, block = 256. 4 LDG.128/thread (mostly L2 hits on kB's output),
// block reduce, scale in place.
__global__ void kC_norm(float* __restrict__ e_io) {
    __shared__ float warp_sums[8];
    const int b   = blockIdx.x;
    const int tid = threadIdx.x;

    cudaGridDependencySynchronize();

    float4* row = reinterpret_cast<float4*>(e_io + (size_t)b * TT);

    float4 v[4];
#pragma unroll
    for (int i = 0; i < 4; ++i) v[i] = row[tid + i * 256];

    float acc = 0.f;
#pragma unroll
    for (int i = 0; i < 4; ++i)
        acc += v[i].x + v[i].y + v[i].z + v[i].w;

#pragma unroll
    for (int off = 16; off > 0; off >>= 1)
        acc += __shfl_down_sync(0xffffffffu, acc, off);
    if ((tid & 31) == 0) warp_sums[tid >> 5] = acc;
    __syncthreads();

    if (tid < 8) {
        float s = warp_sums[tid];
#pragma unroll
        for (int off = 4; off > 0; off >>= 1)
            s += __shfl_down_sync(0xffu, s, off);
        if (tid == 0) warp_sums[0] = s;
    }
    __syncthreads();
    const float inv = 1.f / warp_sums[0];

#pragma unroll
    for (int i = 0; i < 4; ++i) {
        v[i].x *= inv; v[i].y *= inv; v[i].z *= inv; v[i].w *= inv;
        row[tid + i * 256] = v[i];
    }
}

extern "C" void kernel_launch(void* const* d_in, const int* in_sizes, int n_in,
                              void* d_out, int out_size) {
    const float* q    = (const float*)d_in[0];
    const float* k    = (const float*)d_in[1];
    const float* m    = (const float*)d_in[2];
    const float* W    = (const float*)d_in[3];
    const float* bias = (const float*)d_in[4];
    float* out = (float*)d_out;

    // kA: plain launch
    {
        dim3 g(DD / 32, BATCH / 2);
        kA_mids<<<g, 256>>>(q, W);
    }

    // kB: PDL secondary of kA
    {
        cudaLaunchAttribute at[1];
        at[0].id = cudaLaunchAttributeProgrammaticStreamSerialization;
        at[0].val.programmaticStreamSerializationAllowed = 1;
        cudaLaunchConfig_t cfg = {};
        cfg.gridDim  = dim3(TT / 32, BATCH);
        cfg.blockDim = dim3(256);
        cfg.stream   = 0;
        cfg.attrs    = at;
        cfg.numAttrs = 1;
        cudaLaunchKernelEx(&cfg, kB_scores, k, m, bias, out);
    }

    // kC: PDL secondary of kB (launch-latency hiding)
    {
        cudaLaunchAttribute at[1];
        at[0].id = cudaLaunchAttributeProgrammaticStreamSerialization;
        at[0].val.programmaticStreamSerializationAllowed = 1;
        cudaLaunchConfig_t cfg = {};
        cfg.gridDim  = dim3(BATCH);
        cfg.blockDim = dim3(256);
        cfg.stream   = 0;
        cfg.attrs    = at;
        cfg.numAttrs = 1;
        cudaLaunchKernelEx(&cfg, kC_norm, out);
    }
}